// round 14
// baseline (speedup 1.0000x reference)
#include <cuda_runtime.h>
#include <cstdint>

// ---------------- problem constants ----------------
#define Bc   4
#define Cc   256
#define Hc   256
#define Wc   256
#define HWc  65536
#define NHc  8
#define HDc  32
#define Pc   8
#define Gc   32
#define CPGc 8
#define NWIN 1024
#define EPSc 1e-6f
#define ATTN_SCALE 0.17677669529663689f
#define RSQRT2c 0.70710678118654757f

typedef unsigned long long ull;

// ---------------- device scratch (no cudaMalloc allowed) ----------------
__device__ float g_mean[Bc * Gc];
__device__ float g_rstd[Bc * Gc];
__device__ float g_effw[(size_t)Bc * 768 * 256];   // GN-folded qkv weights (tf32-rounded)
__device__ float g_effb[Bc * 768];                 // folded bias (fp32)
__device__ float g_owr[256 * 256];                 // o_w tf32-rounded
__device__ float g_qkv[(size_t)3 * Bc * Cc * HWc]; // [t][b][c][h][w]  (805 MB)
__device__ float g_att[(size_t)Bc * Cc * HWc];     // attention out (256 MB)

// ---------------- helpers ----------------
__device__ __forceinline__ float rna_tf32(float x) {
    uint32_t r;
    asm("cvt.rna.tf32.f32 %0, %1;" : "=r"(r) : "f"(x));
    return __uint_as_float(r);
}
__device__ __forceinline__ uint32_t smem_u32(const void* p) {
    uint32_t a;
    asm("{ .reg .u64 t; cvta.to.shared.u64 t, %1; cvt.u32.u64 %0, t; }" : "=r"(a) : "l"(p));
    return a;
}
__device__ __forceinline__ void cpasync16(uint32_t dst, const void* src) {
    asm volatile("cp.async.cg.shared.global [%0], [%1], 16;" :: "r"(dst), "l"(src) : "memory");
}
__device__ __forceinline__ void mma1688(float* d, const uint32_t* a, uint32_t b0, uint32_t b1) {
    asm volatile(
        "mma.sync.aligned.m16n8k8.row.col.f32.tf32.tf32.f32 "
        "{%0,%1,%2,%3}, {%4,%5,%6,%7}, {%8,%9}, {%0,%1,%2,%3};"
        : "+f"(d[0]), "+f"(d[1]), "+f"(d[2]), "+f"(d[3])
        : "r"(a[0]), "r"(a[1]), "r"(a[2]), "r"(a[3]), "r"(b0), "r"(b1));
}
__device__ __forceinline__ void ldmx4(uint32_t* r, uint32_t addr) {
    asm volatile("ldmatrix.sync.aligned.m8n8.x4.shared.b16 {%0,%1,%2,%3}, [%4];"
        : "=r"(r[0]), "=r"(r[1]), "=r"(r[2]), "=r"(r[3]) : "r"(addr));
}

// ---------------- kernel 1: GroupNorm statistics ----------------
__global__ __launch_bounds__(1024) void gn_stats_kernel(const float* __restrict__ x) {
    int bg = blockIdx.x;
    const float4* p = reinterpret_cast<const float4*>(x) + (size_t)bg * (CPGc * HWc / 4);
    float s = 0.f, ss = 0.f;
    const int n4 = CPGc * HWc / 4;
    for (int i = threadIdx.x; i < n4; i += blockDim.x) {
        float4 v = p[i];
        s  += (v.x + v.y) + (v.z + v.w);
        ss += (v.x * v.x + v.y * v.y) + (v.z * v.z + v.w * v.w);
    }
    const unsigned FULL = 0xffffffffu;
    #pragma unroll
    for (int o = 16; o; o >>= 1) { s += __shfl_down_sync(FULL, s, o); ss += __shfl_down_sync(FULL, ss, o); }
    __shared__ float w1[32], w2[32];
    int lane = threadIdx.x & 31, wid = threadIdx.x >> 5;
    if (lane == 0) { w1[wid] = s; w2[wid] = ss; }
    __syncthreads();
    if (wid == 0) {
        int nw = blockDim.x >> 5;
        s  = (lane < nw) ? w1[lane] : 0.f;
        ss = (lane < nw) ? w2[lane] : 0.f;
        #pragma unroll
        for (int o = 16; o; o >>= 1) { s += __shfl_down_sync(FULL, s, o); ss += __shfl_down_sync(FULL, ss, o); }
        if (lane == 0) {
            const float invN = 1.f / (float)(CPGc * HWc);
            float mu  = s * invN;
            float var = ss * invN - mu * mu;
            g_mean[bg] = mu;
            g_rstd[bg] = rsqrtf(var + EPSc);
        }
    }
}

// ---------------- kernel 2: fold GN into qkv weights (tf32-rounded) ----------------
__global__ __launch_bounds__(256) void effw_kernel(
    const float* __restrict__ qw, const float* __restrict__ kw, const float* __restrict__ vw,
    const float* __restrict__ qb, const float* __restrict__ kb, const float* __restrict__ vb,
    const float* __restrict__ gnw, const float* __restrict__ gnb)
{
    int bo = blockIdx.x;
    int b = bo / 768, o = bo % 768;
    int t = o >> 8, oc = o & 255;
    const float* Wm   = (t == 0) ? qw : ((t == 1) ? kw : vw);
    const float* bias = (t == 0) ? qb : ((t == 1) ? kb : vb);
    int c = threadIdx.x;
    float w  = Wm[oc * 256 + c];
    int g    = c >> 3;
    float rs = g_rstd[b * Gc + g];
    float mu = g_mean[b * Gc + g];
    float sC = rs * gnw[c];
    float tC = gnb[c] - mu * sC;
    g_effw[(size_t)bo * 256 + c] = rna_tf32(w * sC);

    float v = w * tC;
    const unsigned FULL = 0xffffffffu;
    #pragma unroll
    for (int off = 16; off; off >>= 1) v += __shfl_down_sync(FULL, v, off);
    __shared__ float ws[8];
    int lane = c & 31, wid = c >> 5;
    if (lane == 0) ws[wid] = v;
    __syncthreads();
    if (c == 0) {
        float sum = 0.f;
        #pragma unroll
        for (int i = 0; i < 8; i++) sum += ws[i];
        g_effb[bo] = sum + bias[oc];
    }
}

__global__ __launch_bounds__(256) void round_ow_kernel(const float* __restrict__ ow) {
    int j = blockIdx.x * blockDim.x + threadIdx.x; // 16384 float4s
    float4 v = ((const float4*)ow)[j];
    v.x = rna_tf32(v.x); v.y = rna_tf32(v.y);
    v.z = rna_tf32(v.z); v.w = rna_tf32(v.w);
    ((float4*)g_owr)[j] = v;
}

// ---------------- kernels 3 & 5: tf32 mma.sync GEMM ----------------
// C[n][m] = sum_k A[k][m] * W[n][k]  (A m-contiguous). CTA tile 128m x 256n, BK=32.
// 8 warps: warp_m = wid&1 (2), warp_n = wid>>1 (4); warp tile 64x64.
// smem floats per stage: A[32][136] = 4352, B[256][36] = 9216 -> 13568 words, 3 stages.
#define ASTG 4352
#define STGW 13568
#define SM_TOTAL_B (3 * STGW * 4) // 162816 bytes
#define NKI 8

template <bool OCONV>
__global__ void __launch_bounds__(256)
mma_gemm_kernel(const float* __restrict__ Ain, const float* __restrict__ biasin,
                const float* __restrict__ resid, float* __restrict__ outp)
{
    extern __shared__ float sm[];
    const uint32_t sbase = smem_u32(sm);
    const int tid = threadIdx.x, lane = tid & 31, wid = tid >> 5;
    const int warp_m = wid & 1, warp_n = wid >> 1;
    const int ny = blockIdx.x;
    const size_t mbase = (size_t)blockIdx.y * 128;
    const int b = blockIdx.z;

    const float* Ag = (OCONV ? g_att : Ain) + (size_t)b * Cc * HWc + mbase;
    const float* Wg = OCONV ? g_owr : (g_effw + ((size_t)b * 768 + ny * 256) * 256);

    float acc[4][8][4];
    #pragma unroll
    for (int i = 0; i < 4; i++)
        #pragma unroll
        for (int j = 0; j < 8; j++)
            #pragma unroll
            for (int l = 0; l < 4; l++) acc[i][j][l] = 0.f;

    auto issue = [&](int kt, int s) {
        const float* Asrc = Ag + (size_t)kt * 32 * HWc;
        uint32_t Ad = sbase + (uint32_t)(s * STGW) * 4u;
        #pragma unroll
        for (int it = 0; it < 4; it++) {
            int lin = it * 256 + tid;          // 0..1023
            int k = lin >> 5, m4 = (lin & 31) << 2;
            cpasync16(Ad + (uint32_t)(k * 136 + m4) * 4u, Asrc + (size_t)k * HWc + m4);
        }
        const float* Bsrc = Wg + kt * 32;
        uint32_t Bd = sbase + (uint32_t)(s * STGW + ASTG) * 4u;
        #pragma unroll
        for (int it = 0; it < 8; it++) {
            int lin = it * 256 + tid;          // 0..2047
            int n = lin >> 3, k4 = (lin & 7) << 2;
            cpasync16(Bd + (uint32_t)(n * 36 + k4) * 4u, Bsrc + (size_t)n * 256 + k4);
        }
        asm volatile("cp.async.commit_group;" ::: "memory");
    };

    issue(0, 0);
    issue(1, 1);

    const int r = lane >> 2, c = lane & 3;
    const uint32_t boff = ((uint32_t)((lane >> 3) & 1) * 8 + (lane & 7)) * 36 + ((lane >> 4) << 2);

    #pragma unroll 1
    for (int kt = 0; kt < NKI; kt++) {
        const int cur = kt % 3;
        if (kt == NKI - 1) asm volatile("cp.async.wait_group 0;" ::: "memory");
        else               asm volatile("cp.async.wait_group 1;" ::: "memory");
        __syncthreads();
        if (kt + 2 < NKI) issue(kt + 2, (kt + 2) % 3);

        const float* As = sm + cur * STGW;
        const uint32_t Bsu = sbase + (uint32_t)(cur * STGW + ASTG) * 4u
                           + (uint32_t)(warp_n * 64 * 36) * 4u;
        #pragma unroll
        for (int ks = 0; ks < 4; ks++) {
            const int kb = ks * 8;
            uint32_t af[4][4];
            #pragma unroll
            for (int mt = 0; mt < 4; mt++) {
                int m = warp_m * 64 + mt * 16 + r;
                af[mt][0] = __float_as_uint(As[(kb + c) * 136 + m]);
                af[mt][1] = __float_as_uint(As[(kb + c) * 136 + m + 8]);
                af[mt][2] = __float_as_uint(As[(kb + c + 4) * 136 + m]);
                af[mt][3] = __float_as_uint(As[(kb + c + 4) * 136 + m + 8]);
            }
            #pragma unroll
            for (int g = 0; g < 4; g++) {
                uint32_t bf[4];
                ldmx4(bf, Bsu + (uint32_t)(g * 16 * 36 + kb + boff) * 4u);
                #pragma unroll
                for (int mt = 0; mt < 4; mt++) {
                    mma1688(acc[mt][2 * g],     af[mt], bf[0], bf[2]);
                    mma1688(acc[mt][2 * g + 1], af[mt], bf[1], bf[3]);
                }
            }
        }
    }

    // ---------------- epilogue ----------------
    const float* bptr = OCONV ? biasin : (g_effb + b * 768 + ny * 256);
    #pragma unroll
    for (int nt = 0; nt < 8; nt++) {
        int nloc = warp_n * 64 + nt * 8 + 2 * (lane & 3);
        float b0v = bptr[nloc], b1v = bptr[nloc + 1];
        #pragma unroll
        for (int mt = 0; mt < 4; mt++) {
            size_t mg = mbase + warp_m * 64 + mt * 16 + (lane >> 2);
            if (OCONV) {
                size_t o0 = ((size_t)b * Cc + nloc) * HWc + mg;
                size_t o1 = o0 + HWc;
                outp[o0]     = (acc[mt][nt][0] + b0v + resid[o0]) * RSQRT2c;
                outp[o1]     = (acc[mt][nt][1] + b1v + resid[o1]) * RSQRT2c;
                outp[o0 + 8] = (acc[mt][nt][2] + b0v + resid[o0 + 8]) * RSQRT2c;
                outp[o1 + 8] = (acc[mt][nt][3] + b1v + resid[o1 + 8]) * RSQRT2c;
            } else {
                size_t o0 = ((size_t)(ny * Bc + b) * Cc + nloc) * HWc + mg;
                size_t o1 = o0 + HWc;
                g_qkv[o0]     = acc[mt][nt][0] + b0v;
                g_qkv[o1]     = acc[mt][nt][1] + b1v;
                g_qkv[o0 + 8] = acc[mt][nt][2] + b0v;
                g_qkv[o1 + 8] = acc[mt][nt][3] + b1v;
            }
        }
    }
}

// ---------------- kernel 4: pipelined windowed attention via tf32 mma ----------------
// Block = 128 threads per (hpi, head, b); walks 32 windows (wpi) with 2-stage
// cp.async double-buffering. q/k/v staged in natural [hd][tok] layout (stride 72);
// K permutation applied arithmetically at B-fragment read (ptok = Pinv(r4)).
// O bounced through smem [tok][hd] (stride 34) for coalesced float4 STG.
#define AT_STR  72
#define AT_TW   2304                 // words per tensor per stage (32*72)
#define AT_STAGE (3 * AT_TW)         // 6912 words per stage
#define AT_OS   (2 * AT_STAGE)       // os at 13824 words
#define OS_STR  34
#define SM_TOTAL_A ((AT_OS + 64 * OS_STR) * 4)   // 64000 bytes

__global__ __launch_bounds__(128) void attn_mma_kernel() {
    extern __shared__ float sma[];
    const uint32_t sb = smem_u32(sma);
    const int hpi = blockIdx.x, head = blockIdx.y, b = blockIdx.z;
    const int tid = threadIdx.x, lane = tid & 31, wid = tid >> 5;

    const size_t TSTR = (size_t)Bc * Cc * HWc;
    const size_t baseRow = ((size_t)b * Cc + head * HDc) * HWc + (size_t)(hpi * Pc) * Wc;

    // per-thread staging coords (4 float4 per tensor)
    auto issue = [&](int w, int s) {
        const size_t baseW = baseRow + w * Pc;
        #pragma unroll
        for (int it = 0; it < 4; it++) {
            int lin = it * 128 + tid;          // 0..511
            int hd = lin >> 4, row = (lin >> 1) & 7, c4 = (lin & 1) << 2;
            size_t goff = baseW + (size_t)hd * HWc + (size_t)row * Wc + c4;
            uint32_t soff = (uint32_t)(s * AT_STAGE + hd * AT_STR + row * 8 + c4) * 4u;
            cpasync16(sb + soff,                 g_qkv + goff);
            cpasync16(sb + soff + AT_TW * 4u,    g_qkv + TSTR + goff);
            cpasync16(sb + soff + 2 * AT_TW * 4u, g_qkv + 2 * TSTR + goff);
        }
        asm volatile("cp.async.commit_group;" ::: "memory");
    };

    issue(0, 0);

    const int r4 = lane >> 2, cq = lane & 3;
    const int row = wid * 16 + r4;
    const int ptok = (r4 & 1) ? ((r4 + 7) >> 1) : (r4 >> 1);  // Pinv within 8-group
    float* os = sma + AT_OS;
    const unsigned FULL = 0xffffffffu;

    #pragma unroll 1
    for (int w = 0; w < 32; w++) {
        const int s = w & 1;
        if (w + 1 < 32) issue(w + 1, s ^ 1);
        if (w + 1 < 32) asm volatile("cp.async.wait_group 1;" ::: "memory");
        else            asm volatile("cp.async.wait_group 0;" ::: "memory");
        __syncthreads();

        const float* qs = sma + s * AT_STAGE;
        const float* ks = qs + AT_TW;
        const float* vs = qs + 2 * AT_TW;

        // ---- S = Q K^T  (16x64 per warp), K columns permuted via ptok ----
        float sacc[8][4];
        #pragma unroll
        for (int nt = 0; nt < 8; nt++)
            #pragma unroll
            for (int j = 0; j < 4; j++) sacc[nt][j] = 0.f;

        #pragma unroll
        for (int kt = 0; kt < 4; kt++) {
            uint32_t a[4];
            a[0] = __float_as_uint(qs[(kt * 8 + cq) * AT_STR + row]);
            a[1] = __float_as_uint(qs[(kt * 8 + cq) * AT_STR + row + 8]);
            a[2] = __float_as_uint(qs[(kt * 8 + cq + 4) * AT_STR + row]);
            a[3] = __float_as_uint(qs[(kt * 8 + cq + 4) * AT_STR + row + 8]);
            #pragma unroll
            for (int nt = 0; nt < 8; nt++) {
                uint32_t b0 = __float_as_uint(ks[(kt * 8 + cq) * AT_STR + nt * 8 + ptok]);
                uint32_t b1 = __float_as_uint(ks[(kt * 8 + cq + 4) * AT_STR + nt * 8 + ptok]);
                mma1688(sacc[nt], a, b0, b1);
            }
        }

        // ---- softmax (rows row, row+8 per thread; quad reductions) ----
        float mx0 = -3.0e38f, mx1 = -3.0e38f;
        #pragma unroll
        for (int nt = 0; nt < 8; nt++) {
            mx0 = fmaxf(mx0, fmaxf(sacc[nt][0], sacc[nt][1]));
            mx1 = fmaxf(mx1, fmaxf(sacc[nt][2], sacc[nt][3]));
        }
        mx0 = fmaxf(mx0, __shfl_xor_sync(FULL, mx0, 1));
        mx0 = fmaxf(mx0, __shfl_xor_sync(FULL, mx0, 2));
        mx1 = fmaxf(mx1, __shfl_xor_sync(FULL, mx1, 1));
        mx1 = fmaxf(mx1, __shfl_xor_sync(FULL, mx1, 2));

        float sum0 = 0.f, sum1 = 0.f;
        #pragma unroll
        for (int nt = 0; nt < 8; nt++) {
            float e0 = __expf((sacc[nt][0] - mx0) * ATTN_SCALE);
            float e1 = __expf((sacc[nt][1] - mx0) * ATTN_SCALE);
            float e2 = __expf((sacc[nt][2] - mx1) * ATTN_SCALE);
            float e3 = __expf((sacc[nt][3] - mx1) * ATTN_SCALE);
            sacc[nt][0] = e0; sacc[nt][1] = e1; sacc[nt][2] = e2; sacc[nt][3] = e3;
            sum0 += e0 + e1; sum1 += e2 + e3;
        }
        sum0 += __shfl_xor_sync(FULL, sum0, 1);
        sum0 += __shfl_xor_sync(FULL, sum0, 2);
        sum1 += __shfl_xor_sync(FULL, sum1, 1);
        sum1 += __shfl_xor_sync(FULL, sum1, 2);
        const float inv0 = 1.f / sum0, inv1 = 1.f / sum1;

        // ---- O = P V (16x32 per warp); P A-frag = permuted S registers ----
        float oacc[4][4];
        #pragma unroll
        for (int nt = 0; nt < 4; nt++)
            #pragma unroll
            for (int j = 0; j < 4; j++) oacc[nt][j] = 0.f;

        #pragma unroll
        for (int kt = 0; kt < 8; kt++) {
            uint32_t a[4];
            a[0] = __float_as_uint(sacc[kt][0]);
            a[1] = __float_as_uint(sacc[kt][2]);
            a[2] = __float_as_uint(sacc[kt][1]);
            a[3] = __float_as_uint(sacc[kt][3]);
            #pragma unroll
            for (int nt = 0; nt < 4; nt++) {
                uint32_t b0 = __float_as_uint(vs[(nt * 8 + r4) * AT_STR + kt * 8 + cq]);
                uint32_t b1 = __float_as_uint(vs[(nt * 8 + r4) * AT_STR + kt * 8 + cq + 4]);
                mma1688(oacc[nt], a, b0, b1);
            }
        }

        // ---- bounce O through smem, then coalesced float4 STG ----
        const int T0 = row, T1 = row + 8;
        #pragma unroll
        for (int nt = 0; nt < 4; nt++) {
            int hd0 = nt * 8 + 2 * cq;
            *(float2*)(os + T0 * OS_STR + hd0) = make_float2(oacc[nt][0] * inv0, oacc[nt][1] * inv0);
            *(float2*)(os + T1 * OS_STR + hd0) = make_float2(oacc[nt][2] * inv1, oacc[nt][3] * inv1);
        }
        __syncthreads();

        float* og = g_att + baseRow + w * Pc;
        #pragma unroll
        for (int it = 0; it < 4; it++) {
            int lin = it * 128 + tid;
            int hd = lin >> 4, rw = (lin >> 1) & 7, c4 = (lin & 1) << 2;
            int tb = rw * 8 + c4;
            float4 o;
            o.x = os[(tb + 0) * OS_STR + hd];
            o.y = os[(tb + 1) * OS_STR + hd];
            o.z = os[(tb + 2) * OS_STR + hd];
            o.w = os[(tb + 3) * OS_STR + hd];
            *(float4*)(og + (size_t)hd * HWc + (size_t)rw * Wc + c4) = o;
        }
    }
}

// ---------------- launch ----------------
extern "C" void kernel_launch(void* const* d_in, const int* in_sizes, int n_in,
                              void* d_out, int out_size) {
    const float* x    = (const float*)d_in[0];
    const float* gn_w = (const float*)d_in[1];
    const float* gn_b = (const float*)d_in[2];
    const float* q_w  = (const float*)d_in[3];
    const float* q_b  = (const float*)d_in[4];
    const float* k_w  = (const float*)d_in[5];
    const float* k_b  = (const float*)d_in[6];
    const float* v_w  = (const float*)d_in[7];
    const float* v_b  = (const float*)d_in[8];
    const float* o_w  = (const float*)d_in[9];
    const float* o_b  = (const float*)d_in[10];
    float* out = (float*)d_out;

    cudaFuncSetAttribute(mma_gemm_kernel<false>,
                         cudaFuncAttributeMaxDynamicSharedMemorySize, SM_TOTAL_B);
    cudaFuncSetAttribute(mma_gemm_kernel<true>,
                         cudaFuncAttributeMaxDynamicSharedMemorySize, SM_TOTAL_B);
    cudaFuncSetAttribute(attn_mma_kernel,
                         cudaFuncAttributeMaxDynamicSharedMemorySize, SM_TOTAL_A);

    gn_stats_kernel<<<Bc * Gc, 1024>>>(x);
    effw_kernel<<<Bc * 768, 256>>>(q_w, k_w, v_w, q_b, k_b, v_b, gn_w, gn_b);
    round_ow_kernel<<<64, 256>>>(o_w);

    dim3 gq(3, HWc / 128, Bc);
    mma_gemm_kernel<false><<<gq, 256, SM_TOTAL_B>>>(x, nullptr, nullptr, nullptr);

    dim3 ga(Hc / Pc / 1, NHc, Bc);   // (32 hpi, 8 heads, 4 batch) = 1024 blocks
    attn_mma_kernel<<<ga, 128, SM_TOTAL_A>>>();

    dim3 go(1, HWc / 128, Bc);
    mma_gemm_kernel<true><<<go, 256, SM_TOTAL_B>>>(nullptr, o_b, x, out);
}

// round 16
// speedup vs baseline: 1.3671x; 1.3671x over previous
#include <cuda_runtime.h>
#include <cuda_fp16.h>
#include <cstdint>

// ---------------- problem constants ----------------
#define Bc   4
#define Cc   256
#define Hc   256
#define Wc   256
#define HWc  65536
#define NHc  8
#define HDc  32
#define Pc   8
#define Gc   32
#define CPGc 8
#define EPSc 1e-6f
#define ATTN_SCALE 0.17677669529663689f
#define RSQRT2c 0.70710678118654757f

// ---------------- device scratch (no cudaMalloc allowed) ----------------
__device__ float  g_mean[Bc * Gc];
__device__ float  g_rstd[Bc * Gc];
__device__ __half g_effwh[(size_t)Bc * 768 * 256];  // GN-folded qkv weights, fp16
__device__ float  g_effb[Bc * 768];                 // folded bias (fp32)
__device__ __half g_owh[256 * 256];                 // o_w fp16
__device__ __half g_xh[(size_t)Bc * HWc * Cc];      // x transposed [b][hw][c] fp16 (128MB)
__device__ __half g_qkvh[(size_t)Bc * HWc * 768];   // qkv [b][hw][768] fp16 (402MB)
__device__ __half g_atth[(size_t)Bc * HWc * Cc];    // attention out [b][hw][c] fp16 (128MB)

// ---------------- helpers ----------------
__device__ __forceinline__ uint32_t smem_u32(const void* p) {
    uint32_t a;
    asm("{ .reg .u64 t; cvta.to.shared.u64 t, %1; cvt.u32.u64 %0, t; }" : "=r"(a) : "l"(p));
    return a;
}
__device__ __forceinline__ void cpasync16(uint32_t dst, const void* src) {
    asm volatile("cp.async.cg.shared.global [%0], [%1], 16;" :: "r"(dst), "l"(src) : "memory");
}
__device__ __forceinline__ uint32_t h2pack(float a, float b) {
    __half2 h = __floats2half2_rn(a, b);
    return *reinterpret_cast<uint32_t*>(&h);
}
__device__ __forceinline__ void mma16816(float* d, const uint32_t* a, uint32_t b0, uint32_t b1) {
    asm volatile(
        "mma.sync.aligned.m16n8k16.row.col.f32.f16.f16.f32 "
        "{%0,%1,%2,%3}, {%4,%5,%6,%7}, {%8,%9}, {%0,%1,%2,%3};"
        : "+f"(d[0]), "+f"(d[1]), "+f"(d[2]), "+f"(d[3])
        : "r"(a[0]), "r"(a[1]), "r"(a[2]), "r"(a[3]), "r"(b0), "r"(b1));
}
__device__ __forceinline__ void ldmx4(uint32_t* r, uint32_t addr) {
    asm volatile("ldmatrix.sync.aligned.m8n8.x4.shared.b16 {%0,%1,%2,%3}, [%4];"
        : "=r"(r[0]), "=r"(r[1]), "=r"(r[2]), "=r"(r[3]) : "r"(addr));
}
__device__ __forceinline__ void ldmx4t(uint32_t* r, uint32_t addr) {
    asm volatile("ldmatrix.sync.aligned.m8n8.x4.trans.shared.b16 {%0,%1,%2,%3}, [%4];"
        : "=r"(r[0]), "=r"(r[1]), "=r"(r[2]), "=r"(r[3]) : "r"(addr));
}

// ---------------- kernel 1: GroupNorm statistics ----------------
__global__ __launch_bounds__(1024) void gn_stats_kernel(const float* __restrict__ x) {
    int bg = blockIdx.x;
    const float4* p = reinterpret_cast<const float4*>(x) + (size_t)bg * (CPGc * HWc / 4);
    float s = 0.f, ss = 0.f;
    const int n4 = CPGc * HWc / 4;
    for (int i = threadIdx.x; i < n4; i += blockDim.x) {
        float4 v = p[i];
        s  += (v.x + v.y) + (v.z + v.w);
        ss += (v.x * v.x + v.y * v.y) + (v.z * v.z + v.w * v.w);
    }
    const unsigned FULL = 0xffffffffu;
    #pragma unroll
    for (int o = 16; o; o >>= 1) { s += __shfl_down_sync(FULL, s, o); ss += __shfl_down_sync(FULL, ss, o); }
    __shared__ float w1[32], w2[32];
    int lane = threadIdx.x & 31, wid = threadIdx.x >> 5;
    if (lane == 0) { w1[wid] = s; w2[wid] = ss; }
    __syncthreads();
    if (wid == 0) {
        int nw = blockDim.x >> 5;
        s  = (lane < nw) ? w1[lane] : 0.f;
        ss = (lane < nw) ? w2[lane] : 0.f;
        #pragma unroll
        for (int o = 16; o; o >>= 1) { s += __shfl_down_sync(FULL, s, o); ss += __shfl_down_sync(FULL, ss, o); }
        if (lane == 0) {
            const float invN = 1.f / (float)(CPGc * HWc);
            float mu  = s * invN;
            float var = ss * invN - mu * mu;
            g_mean[bg] = mu;
            g_rstd[bg] = rsqrtf(var + EPSc);
        }
    }
}

// ---------------- kernel 1b: transpose+convert x -> g_xh [b][hw][c] fp16 ----------------
#define XT_STR 72
__global__ __launch_bounds__(256) void xpose_kernel(const float* __restrict__ x) {
    __shared__ __half ts[64 * XT_STR];
    const int hwb = blockIdx.x * 64, cb = blockIdx.y * 64, b = blockIdx.z;
    const float* xp = x + (size_t)b * Cc * HWc;
    const int tid = threadIdx.x;
    #pragma unroll
    for (int it = 0; it < 4; it++) {
        int lin = it * 256 + tid;          // 1024 = c(64) x f4(16)
        int c = lin >> 4, f4 = lin & 15;
        float4 v = *(const float4*)(xp + (size_t)(cb + c) * HWc + hwb + f4 * 4);
        int cc = c >> 3, cl = c & 7;
        const float* vf = (const float*)&v;
        #pragma unroll
        for (int i = 0; i < 4; i++) {
            int hw = f4 * 4 + i;
            int chunk = cc ^ (hw & 7);
            ts[hw * XT_STR + chunk * 8 + cl] = __float2half_rn(vf[i]);
        }
    }
    __syncthreads();
    __half* dst = g_xh + (size_t)b * HWc * Cc;
    #pragma unroll
    for (int it = 0; it < 2; it++) {
        int lin = it * 256 + tid;          // 512 = hw(64) x kc(8)
        int hw = lin >> 3, kc = lin & 7;
        int chunk = kc ^ (hw & 7);
        uint4 vv = *(const uint4*)&ts[hw * XT_STR + chunk * 8];
        *(uint4*)(dst + (size_t)(hwb + hw) * Cc + cb + kc * 8) = vv;
    }
}

// ---------------- kernel 2: fold GN into qkv weights (fp16) ----------------
__global__ __launch_bounds__(256) void effw_kernel(
    const float* __restrict__ qw, const float* __restrict__ kw, const float* __restrict__ vw,
    const float* __restrict__ qb, const float* __restrict__ kb, const float* __restrict__ vb,
    const float* __restrict__ gnw, const float* __restrict__ gnb)
{
    int bo = blockIdx.x;
    int b = bo / 768, o = bo % 768;
    int t = o >> 8, oc = o & 255;
    const float* Wm   = (t == 0) ? qw : ((t == 1) ? kw : vw);
    const float* bias = (t == 0) ? qb : ((t == 1) ? kb : vb);
    int c = threadIdx.x;
    float w  = Wm[oc * 256 + c];
    int g    = c >> 3;
    float rs = g_rstd[b * Gc + g];
    float mu = g_mean[b * Gc + g];
    float sC = rs * gnw[c];
    float tC = gnb[c] - mu * sC;
    g_effwh[(size_t)bo * 256 + c] = __float2half_rn(w * sC);

    float v = w * tC;
    const unsigned FULL = 0xffffffffu;
    #pragma unroll
    for (int off = 16; off; off >>= 1) v += __shfl_down_sync(FULL, v, off);
    __shared__ float ws[8];
    int lane = c & 31, wid = c >> 5;
    if (lane == 0) ws[wid] = v;
    __syncthreads();
    if (c == 0) {
        float sum = 0.f;
        #pragma unroll
        for (int i = 0; i < 8; i++) sum += ws[i];
        g_effb[bo] = sum + bias[oc];
    }
}

__global__ __launch_bounds__(256) void cvt_ow_kernel(const float* __restrict__ ow) {
    int j = blockIdx.x * 256 + threadIdx.x;   // 16384 float4s
    float4 v = ((const float4*)ow)[j];
    uint2 o;
    o.x = h2pack(v.x, v.y);
    o.y = h2pack(v.z, v.w);
    *(uint2*)(g_owh + (size_t)j * 4) = o;
}

// ---------------- kernels 3 & 5: fp16 mma.sync GEMM ----------------
// D[m][n] = sum_k A[m][k] * W[n][k]; A,W fp16 k-contiguous. CTA 128m x 256n, BK=32.
// 8 warps: warp_m = wid&1, warp_n = wid>>1; warp tile 64x64. 3-stage cp.async.
// smem: A[128][40]h (10240B) + B[256][40]h (20480B) per stage.
#define AST_B 10240
#define STG_B 30720
#define SM_TOTAL_B (3 * STG_B)
#define NKI 8

template <bool OCONV>
__global__ void __launch_bounds__(256)
mma_gemm_kernel(const float* __restrict__ biasin, const float* __restrict__ resid,
                float* __restrict__ outp)
{
    extern __shared__ char smc[];
    const uint32_t sbase = smem_u32(smc);
    const int tid = threadIdx.x, lane = tid & 31, wid = tid >> 5;
    const int warp_m = wid & 1, warp_n = wid >> 1;
    const int ny = blockIdx.x;
    const size_t mbase = (size_t)blockIdx.y * 128;
    const int b = blockIdx.z;

    const __half* Ag = (OCONV ? g_atth : g_xh) + (size_t)b * HWc * Cc;
    const __half* Wg = OCONV ? g_owh : (g_effwh + ((size_t)b * 768 + ny * 256) * 256);

    float acc[4][8][4];
    #pragma unroll
    for (int i = 0; i < 4; i++)
        #pragma unroll
        for (int j = 0; j < 8; j++)
            #pragma unroll
            for (int l = 0; l < 4; l++) acc[i][j][l] = 0.f;

    auto issue = [&](int kt, int s) {
        // A: 128 rows x 4 chunks of 16B  (512 chunks / 256 thr = 2 each)
        #pragma unroll
        for (int it = 0; it < 2; it++) {
            int lin = it * 256 + tid;
            int row = lin >> 2, kc = lin & 3;
            cpasync16(sbase + (uint32_t)(s * STG_B + row * 80 + kc * 16),
                      Ag + (mbase + row) * 256 + kt * 32 + kc * 8);
        }
        // B: 256 rows x 4 chunks (1024 / 256 = 4 each)
        #pragma unroll
        for (int it = 0; it < 4; it++) {
            int lin = it * 256 + tid;
            int row = lin >> 2, kc = lin & 3;
            cpasync16(sbase + (uint32_t)(s * STG_B + AST_B + row * 80 + kc * 16),
                      Wg + (size_t)row * 256 + kt * 32 + kc * 8);
        }
        asm volatile("cp.async.commit_group;" ::: "memory");
    };

    issue(0, 0);
    issue(1, 1);

    const uint32_t aoff = (uint32_t)((lane & 15) * 80 + (lane >> 4) * 16);

    #pragma unroll 1
    for (int kt = 0; kt < NKI; kt++) {
        const int cur = kt % 3;
        if (kt == NKI - 1) asm volatile("cp.async.wait_group 0;" ::: "memory");
        else               asm volatile("cp.async.wait_group 1;" ::: "memory");
        __syncthreads();
        if (kt + 2 < NKI) issue(kt + 2, (kt + 2) % 3);

        const uint32_t Asm = sbase + (uint32_t)(cur * STG_B) + (uint32_t)(warp_m * 64 * 80);
        const uint32_t Bsm = sbase + (uint32_t)(cur * STG_B + AST_B) + (uint32_t)(warp_n * 64 * 80);
        #pragma unroll
        for (int ks = 0; ks < 2; ks++) {
            const uint32_t kbB = ks * 32;
            uint32_t af[4][4];
            #pragma unroll
            for (int mt = 0; mt < 4; mt++)
                ldmx4(af[mt], Asm + (uint32_t)(mt * 16 * 80) + kbB + aoff);
            #pragma unroll
            for (int g = 0; g < 4; g++) {
                uint32_t bf[4];
                ldmx4(bf, Bsm + (uint32_t)(g * 16 * 80) + kbB + aoff);
                #pragma unroll
                for (int mt = 0; mt < 4; mt++) {
                    mma16816(acc[mt][2 * g],     af[mt], bf[0], bf[2]);
                    mma16816(acc[mt][2 * g + 1], af[mt], bf[1], bf[3]);
                }
            }
        }
    }

    // ---------------- epilogue ----------------
    if (OCONV) {
        #pragma unroll
        for (int nt = 0; nt < 8; nt++) {
            int nloc = warp_n * 64 + nt * 8 + 2 * (lane & 3);
            float b0v = biasin[nloc], b1v = biasin[nloc + 1];
            #pragma unroll
            for (int mt = 0; mt < 4; mt++) {
                size_t mg = mbase + warp_m * 64 + mt * 16 + (lane >> 2);
                size_t o0 = ((size_t)b * Cc + nloc) * HWc + mg;
                size_t o1 = o0 + HWc;
                outp[o0]     = (acc[mt][nt][0] + b0v + resid[o0]) * RSQRT2c;
                outp[o1]     = (acc[mt][nt][1] + b1v + resid[o1]) * RSQRT2c;
                outp[o0 + 8] = (acc[mt][nt][2] + b0v + resid[o0 + 8]) * RSQRT2c;
                outp[o1 + 8] = (acc[mt][nt][3] + b1v + resid[o1 + 8]) * RSQRT2c;
            }
        }
    } else {
        __half* dq = g_qkvh + (size_t)b * HWc * 768 + ny * 256;
        const float* bptr = g_effb + b * 768 + ny * 256;
        #pragma unroll
        for (int nt = 0; nt < 8; nt++) {
            int nloc = warp_n * 64 + nt * 8 + 2 * (lane & 3);
            float b0v = bptr[nloc], b1v = bptr[nloc + 1];
            #pragma unroll
            for (int mt = 0; mt < 4; mt++) {
                size_t mg = mbase + warp_m * 64 + mt * 16 + (lane >> 2);
                *(uint32_t*)(dq + mg * 768 + nloc)       = h2pack(acc[mt][nt][0] + b0v, acc[mt][nt][1] + b1v);
                *(uint32_t*)(dq + (mg + 8) * 768 + nloc) = h2pack(acc[mt][nt][2] + b0v, acc[mt][nt][3] + b1v);
            }
        }
    }
}

// ---------------- kernel 4: windowed attention via fp16 mma ----------------
// Block = 128 threads (4 warps) per (window, head, batch). Warp w: rows [16w,16w+16).
// q/k/v staged [tok][hd] half (stride 40h). No K permutation needed in fp16:
// S fragments pack k-adjacent pairs, so P converts directly to PV A-frags; V via ldmatrix.trans.
__global__ __launch_bounds__(128) void attn_mma_kernel() {
    __shared__ __half qs[64 * 40], ksm[64 * 40], vsm[64 * 40], os[64 * 40];
    const int win = blockIdx.x, head = blockIdx.y, b = blockIdx.z;
    const int hpi = win >> 5, wpi = win & 31;
    const int tid = threadIdx.x, lane = tid & 31, wid = tid >> 5;

    const __half* qkv = g_qkvh + (size_t)b * HWc * 768;
    const uint32_t qsb = smem_u32(qs), ksb = smem_u32(ksm), vsb = smem_u32(vsm);

    #pragma unroll
    for (int it = 0; it < 2; it++) {
        int lin = it * 128 + tid;          // 256 = tok(64) x kc(4)
        int tok = lin >> 2, kc = lin & 3;
        int hw = (hpi * 8 + (tok >> 3)) * 256 + wpi * 8 + (tok & 7);
        const __half* srow = qkv + (size_t)hw * 768 + head * 32 + kc * 8;
        uint32_t dst = (uint32_t)(tok * 80 + kc * 16);
        cpasync16(qsb + dst, srow);
        cpasync16(ksb + dst, srow + 256);
        cpasync16(vsb + dst, srow + 512);
    }
    asm volatile("cp.async.commit_group;" ::: "memory");
    asm volatile("cp.async.wait_group 0;" ::: "memory");
    __syncthreads();

    const int r4 = lane >> 2, cq = lane & 3;
    const int row0 = wid * 16;
    const uint32_t aoff = (uint32_t)((lane & 15) * 80 + (lane >> 4) * 16);
    const unsigned FULL = 0xffffffffu;

    // ---- S = Q K^T (16x64 per warp), k = hd 32 = 2 k16-steps ----
    float sacc[8][4];
    #pragma unroll
    for (int nt = 0; nt < 8; nt++)
        #pragma unroll
        for (int j = 0; j < 4; j++) sacc[nt][j] = 0.f;

    #pragma unroll
    for (int kt = 0; kt < 2; kt++) {
        uint32_t af[4];
        ldmx4(af, qsb + (uint32_t)(row0 * 80 + kt * 32) + aoff);
        #pragma unroll
        for (int g = 0; g < 4; g++) {
            uint32_t bf[4];
            ldmx4(bf, ksb + (uint32_t)(g * 16 * 80 + kt * 32) + aoff);
            mma16816(sacc[2 * g],     af, bf[0], bf[2]);
            mma16816(sacc[2 * g + 1], af, bf[1], bf[3]);
        }
    }

    // ---- softmax (rows row0+r4 and +8; quad reductions) ----
    float mx0 = -3.0e38f, mx1 = -3.0e38f;
    #pragma unroll
    for (int nt = 0; nt < 8; nt++) {
        mx0 = fmaxf(mx0, fmaxf(sacc[nt][0], sacc[nt][1]));
        mx1 = fmaxf(mx1, fmaxf(sacc[nt][2], sacc[nt][3]));
    }
    mx0 = fmaxf(mx0, __shfl_xor_sync(FULL, mx0, 1));
    mx0 = fmaxf(mx0, __shfl_xor_sync(FULL, mx0, 2));
    mx1 = fmaxf(mx1, __shfl_xor_sync(FULL, mx1, 1));
    mx1 = fmaxf(mx1, __shfl_xor_sync(FULL, mx1, 2));

    float sum0 = 0.f, sum1 = 0.f;
    #pragma unroll
    for (int nt = 0; nt < 8; nt++) {
        float e0 = __expf((sacc[nt][0] - mx0) * ATTN_SCALE);
        float e1 = __expf((sacc[nt][1] - mx0) * ATTN_SCALE);
        float e2 = __expf((sacc[nt][2] - mx1) * ATTN_SCALE);
        float e3 = __expf((sacc[nt][3] - mx1) * ATTN_SCALE);
        sacc[nt][0] = e0; sacc[nt][1] = e1; sacc[nt][2] = e2; sacc[nt][3] = e3;
        sum0 += e0 + e1; sum1 += e2 + e3;
    }
    sum0 += __shfl_xor_sync(FULL, sum0, 1);
    sum0 += __shfl_xor_sync(FULL, sum0, 2);
    sum1 += __shfl_xor_sync(FULL, sum1, 1);
    sum1 += __shfl_xor_sync(FULL, sum1, 2);
    const float inv0 = 1.f / sum0, inv1 = 1.f / sum1;

    // ---- O = P V (16x32 per warp); P folded with 1/sum, fp16 A-frags ----
    float oacc[4][4];
    #pragma unroll
    for (int nt = 0; nt < 4; nt++)
        #pragma unroll
        for (int j = 0; j < 4; j++) oacc[nt][j] = 0.f;

    #pragma unroll
    for (int g = 0; g < 4; g++) {
        uint32_t aP[4];
        aP[0] = h2pack(sacc[2 * g][0] * inv0,     sacc[2 * g][1] * inv0);
        aP[1] = h2pack(sacc[2 * g][2] * inv1,     sacc[2 * g][3] * inv1);
        aP[2] = h2pack(sacc[2 * g + 1][0] * inv0, sacc[2 * g + 1][1] * inv0);
        aP[3] = h2pack(sacc[2 * g + 1][2] * inv1, sacc[2 * g + 1][3] * inv1);
        uint32_t bf[4];
        ldmx4t(bf, vsb + (uint32_t)(g * 16 * 80) + aoff);
        mma16816(oacc[0], aP, bf[0], bf[1]);
        mma16816(oacc[1], aP, bf[2], bf[3]);
        ldmx4t(bf, vsb + (uint32_t)(g * 16 * 80 + 32) + aoff);
        mma16816(oacc[2], aP, bf[0], bf[1]);
        mma16816(oacc[3], aP, bf[2], bf[3]);
    }

    // ---- bounce O through smem (fp16), then 16B-coalesced STG ----
    const int T0 = row0 + r4, T1 = T0 + 8;
    #pragma unroll
    for (int nt = 0; nt < 4; nt++) {
        int hd0 = nt * 8 + 2 * cq;
        *(uint32_t*)&os[T0 * 40 + hd0] = h2pack(oacc[nt][0], oacc[nt][1]);
        *(uint32_t*)&os[T1 * 40 + hd0] = h2pack(oacc[nt][2], oacc[nt][3]);
    }
    __syncthreads();

    __half* og = g_atth + (size_t)b * HWc * Cc;
    #pragma unroll
    for (int it = 0; it < 2; it++) {
        int lin = it * 128 + tid;
        int tok = lin >> 2, kc = lin & 3;
        int hw = (hpi * 8 + (tok >> 3)) * 256 + wpi * 8 + (tok & 7);
        uint4 vv = *(const uint4*)&os[tok * 40 + kc * 8];
        *(uint4*)(og + (size_t)hw * 256 + head * 32 + kc * 8) = vv;
    }
}

// ---------------- launch ----------------
extern "C" void kernel_launch(void* const* d_in, const int* in_sizes, int n_in,
                              void* d_out, int out_size) {
    const float* x    = (const float*)d_in[0];
    const float* gn_w = (const float*)d_in[1];
    const float* gn_b = (const float*)d_in[2];
    const float* q_w  = (const float*)d_in[3];
    const float* q_b  = (const float*)d_in[4];
    const float* k_w  = (const float*)d_in[5];
    const float* k_b  = (const float*)d_in[6];
    const float* v_w  = (const float*)d_in[7];
    const float* v_b  = (const float*)d_in[8];
    const float* o_w  = (const float*)d_in[9];
    const float* o_b  = (const float*)d_in[10];
    float* out = (float*)d_out;

    cudaFuncSetAttribute(mma_gemm_kernel<false>,
                         cudaFuncAttributeMaxDynamicSharedMemorySize, SM_TOTAL_B);
    cudaFuncSetAttribute(mma_gemm_kernel<true>,
                         cudaFuncAttributeMaxDynamicSharedMemorySize, SM_TOTAL_B);

    gn_stats_kernel<<<Bc * Gc, 1024>>>(x);
    xpose_kernel<<<dim3(HWc / 64, Cc / 64, Bc), 256>>>(x);
    effw_kernel<<<Bc * 768, 256>>>(q_w, k_w, v_w, q_b, k_b, v_b, gn_w, gn_b);
    cvt_ow_kernel<<<64, 256>>>(o_w);

    dim3 gq(3, HWc / 128, Bc);
    mma_gemm_kernel<false><<<gq, 256, SM_TOTAL_B>>>(nullptr, nullptr, nullptr);

    dim3 ga(1024, NHc, Bc);
    attn_mma_kernel<<<ga, 128>>>();

    dim3 go(1, HWc / 128, Bc);
    mma_gemm_kernel<true><<<go, 256, SM_TOTAL_B>>>(o_b, x, out);
}